// round 16
// baseline (speedup 1.0000x reference)
#include <cuda_runtime.h>
#include <cuda_bf16.h>
#include <cstdint>

// ===========================================================================
// Sparse conv encoder, mma.sync bf16 hi/lo x3.
// conv1/conv2: per-tap COMPACTED gather-GEMM (swizzled smem, 3 CTAs/SM,
//   split-gather pipeline, fused atomic-emit prep, scatter/stream contrib).
// conv3: dense cp.async pipeline (R14 form).
// R16: BN statistics fused into conv2's reduce (bn_partial pass removed).
// ===========================================================================

#define MAXN 60032
#define KT1 27
#define KT2 8

__device__ __nv_bfloat16 g_x_hi[MAXN * 96];
__device__ __nv_bfloat16 g_x_lo[MAXN * 96];
__device__ __nv_bfloat16 g_f1_hi[MAXN * 64];
__device__ __nv_bfloat16 g_f1_lo[MAXN * 64];
__device__ __nv_bfloat16 g_f2_hi[MAXN * 64];
__device__ __nv_bfloat16 g_f2_lo[MAXN * 64];
__device__ __nv_bfloat16 g_w1_hi[27 * 96 * 64];
__device__ __nv_bfloat16 g_w1_lo[27 * 96 * 64];
__device__ __nv_bfloat16 g_w2_hi[8 * 64 * 64];
__device__ __nv_bfloat16 g_w2_lo[8 * 64 * 64];
__device__ __nv_bfloat16 g_w3_hi[27 * 64 * 64];
__device__ __nv_bfloat16 g_w3_lo[27 * 64 * 64];
__device__ float g_st[128];
__device__ float g_bnpart[7552 * 128];           // per-block BN partials

// compaction structures
__device__ int   g_mask1[MAXN];
__device__ int   g_mask2[MAXN];
__device__ int   g_tapcnt1[KT1];
__device__ int   g_tapcnt2[KT2];
__device__ int   g_pairidx1[KT1 * MAXN];
__device__ int   g_pairdst1[KT1 * MAXN];         // (row<<5)|j
__device__ int   g_pairidx2[KT2 * MAXN];
__device__ int   g_pairdst2[KT2 * MAXN];         // (row<<3)|j
__device__ float g_contrib[(size_t)MAXN * 32 * 64];

__device__ __forceinline__ uint32_t smem_u32(const void* p) {
    uint32_t a;
    asm("{ .reg .u64 t; cvta.to.shared.u64 t, %1; cvt.u32.u64 %0, t; }"
        : "=r"(a) : "l"(p));
    return a;
}
__device__ __forceinline__ void cp16(uint32_t s, const void* g, int sz) {
    asm volatile("cp.async.cg.shared.global [%0], [%1], 16, %2;"
                 :: "r"(s), "l"(g), "r"(sz) : "memory");
}
__device__ __forceinline__ void cp_commit() {
    asm volatile("cp.async.commit_group;" ::: "memory");
}
template <int N>
__device__ __forceinline__ void cp_wait() {
    asm volatile("cp.async.wait_group %0;" :: "n"(N) : "memory");
}
__device__ __forceinline__ void ldsm_x4(uint32_t* r, uint32_t addr) {
    asm volatile("ldmatrix.sync.aligned.m8n8.x4.shared.b16 {%0,%1,%2,%3}, [%4];"
                 : "=r"(r[0]), "=r"(r[1]), "=r"(r[2]), "=r"(r[3]) : "r"(addr));
}
__device__ __forceinline__ void ldsm_x4_t(uint32_t* r, uint32_t addr) {
    asm volatile("ldmatrix.sync.aligned.m8n8.x4.trans.shared.b16 {%0,%1,%2,%3}, [%4];"
                 : "=r"(r[0]), "=r"(r[1]), "=r"(r[2]), "=r"(r[3]) : "r"(addr));
}
__device__ __forceinline__ void mma_bf16(float* d, const uint32_t* a, const uint32_t* b) {
    asm volatile(
        "mma.sync.aligned.m16n8k16.row.col.f32.bf16.bf16.f32 "
        "{%0,%1,%2,%3}, {%4,%5,%6,%7}, {%8,%9}, {%0,%1,%2,%3};"
        : "+f"(d[0]), "+f"(d[1]), "+f"(d[2]), "+f"(d[3])
        : "r"(a[0]), "r"(a[1]), "r"(a[2]), "r"(a[3]), "r"(b[0]), "r"(b[1]));
}

// 16B-chunk XOR swizzles (same formula for cp.async write and ldmatrix read)
template <int CIN>
__device__ __forceinline__ int swzA(int c, int r) {
    return (CIN == 96) ? (c ^ ((r >> 1) & 3)) : (c ^ (r & 7));
}
__device__ __forceinline__ int swzB(int c, int r) { return c ^ (r & 7); }

// ===========================================================================
// Fused compaction (templated): mask + block histogram + atomic base + emit.
// ===========================================================================
template <int KT, int SHIFT>
__global__ __launch_bounds__(256) void emit_fused(
    const int* __restrict__ nmap, int n, int n_in,
    int* __restrict__ maskp, int* __restrict__ tapcnt,
    int* __restrict__ pairidx, int* __restrict__ pairdst)
{
    const int t = threadIdx.x, lane = t & 31, w = t >> 5;
    const int row = blockIdx.x * 256 + t;

    int idxs[KT];
    unsigned m = 0;
    if (row < n) {
        #pragma unroll
        for (int k = 0; k < KT; ++k) {
            idxs[k] = __ldg(&nmap[(size_t)row * KT + k]);
            if (idxs[k] < n_in) m |= 1u << k;
        }
        maskp[row] = (int)m;
    }

    __shared__ int hist[KT], base[KT], wt[KT][8];
    if (t < KT) hist[t] = 0;
    __syncthreads();
    #pragma unroll
    for (int k = 0; k < KT; ++k) {
        const unsigned bal = __ballot_sync(0xffffffffu, (m >> k) & 1);
        if (lane == 0) { wt[k][w] = __popc(bal); if (bal) atomicAdd(&hist[k], __popc(bal)); }
    }
    __syncthreads();
    if (t < KT) base[t] = atomicAdd(&tapcnt[t], hist[t]);
    __syncthreads();

    int j = 0;
    #pragma unroll
    for (int k = 0; k < KT; ++k) {
        const int valid = (m >> k) & 1;
        const unsigned bal = __ballot_sync(0xffffffffu, valid);
        if (valid) {
            int wb = 0;
            #pragma unroll
            for (int i = 0; i < 8; ++i) if (i < w) wb += wt[k][i];
            const int rank = wb + __popc(bal & ((1u << lane) - 1u));
            const int pos  = k * MAXN + base[k] + rank;
            pairidx[pos] = idxs[k];
            pairdst[pos] = (row << SHIFT) | j;
            ++j;
        }
    }
}

// ===========================================================================
// Compact GEMM, swizzled smem, split-gather pipeline (R14 config).
// ===========================================================================
template <int CIN>
__global__ __launch_bounds__(256, 3) void conv_compact(
    const __nv_bfloat16* __restrict__ a_hi, const __nv_bfloat16* __restrict__ a_lo,
    const __nv_bfloat16* __restrict__ w_hi, const __nv_bfloat16* __restrict__ w_lo,
    const int* __restrict__ tapcnt,
    const int* __restrict__ pairidx, const int* __restrict__ pairdst)
{
    constexpr int KSTEPS = CIN / 16;
    constexpr int KH = KSTEPS / 2;
    constexpr int CPR = CIN / 8;
    constexpr int CPRH = CPR / 2;
    constexpr uint32_t OFF_ALO = (uint32_t)(128 * CIN) * 2;
    constexpr uint32_t OFF_BHI = 2 * OFF_ALO;
    constexpr uint32_t OFF_BLO = OFF_BHI + (uint32_t)(CIN * 64) * 2;

    const int k = blockIdx.y;
    const int tot = __ldg(&tapcnt[k]);
    const int tilestart = blockIdx.x * 128;
    if (tilestart >= tot) return;
    const int q0 = k * MAXN + tilestart;

    extern __shared__ __align__(16) __nv_bfloat16 smem[];
    const uint32_t sb = smem_u32(smem);
    const int tid = threadIdx.x, wid = tid >> 5, lane = tid & 31;
    const int wm = (wid >> 1) * 32, wn = (wid & 1) * 32;
    const int lrow = lane & 15, lhalf = lane >> 4;

    #pragma unroll 2
    for (int i = tid; i < 2 * 128 * CPRH; i += 256) {
        const int buf = i / (128 * CPRH);
        const int j   = i % (128 * CPRH);
        const int r   = j / CPRH, c = j % CPRH;
        const int ok  = tilestart + r < tot;
        const int idx = ok ? __ldg(&pairidx[q0 + r]) : 0;
        const __nv_bfloat16* src = (buf ? a_lo : a_hi) + (size_t)idx * CIN + c * 8;
        cp16(sb + (buf ? OFF_ALO : 0u)
             + (uint32_t)(r * CPR + swzA<CIN>(c, r)) * 16, src, ok ? 16 : 0);
    }
    #pragma unroll 2
    for (int i = tid; i < 2 * CIN * 8; i += 256) {
        const int buf = i / (CIN * 8);
        const int j   = i % (CIN * 8);
        const int r   = j >> 3, c = j & 7;
        const __nv_bfloat16* src = (buf ? w_lo : w_hi)
            + (size_t)k * CIN * 64 + r * 64 + c * 8;
        cp16(sb + (buf ? OFF_BLO : OFF_BHI)
             + (uint32_t)(r * 8 + swzB(c, r)) * 16, src, 16);
    }
    cp_commit();

    #pragma unroll 2
    for (int i = tid; i < 2 * 128 * CPRH; i += 256) {
        const int buf = i / (128 * CPRH);
        const int j   = i % (128 * CPRH);
        const int r   = j / CPRH, c = j % CPRH + CPRH;
        const int ok  = tilestart + r < tot;
        const int idx = ok ? __ldg(&pairidx[q0 + r]) : 0;
        const __nv_bfloat16* src = (buf ? a_lo : a_hi) + (size_t)idx * CIN + c * 8;
        cp16(sb + (buf ? OFF_ALO : 0u)
             + (uint32_t)(r * CPR + swzA<CIN>(c, r)) * 16, src, ok ? 16 : 0);
    }
    cp_commit();

    float acc[2][4][4] = {};

    auto mma_range = [&](int s0, int s1) {
        for (int s = s0; s < s1; ++s) {
            uint32_t ah[2][4], al[2][4];
            #pragma unroll
            for (int mt = 0; mt < 2; ++mt) {
                const int row = wm + mt * 16 + lrow;
                const uint32_t off =
                    (uint32_t)(row * CPR + swzA<CIN>(2 * s + lhalf, row)) * 16;
                ldsm_x4(ah[mt], sb + off);
                ldsm_x4(al[mt], sb + OFF_ALO + off);
            }
            uint32_t bh[2][4], bl[2][4];
            #pragma unroll
            for (int p = 0; p < 2; ++p) {
                const int rk = s * 16 + lrow;
                const int cb = (wn >> 3) + 2 * p + lhalf;
                const uint32_t off = (uint32_t)(rk * 8 + swzB(cb, rk)) * 16;
                ldsm_x4_t(bh[p], sb + OFF_BHI + off);
                ldsm_x4_t(bl[p], sb + OFF_BLO + off);
            }
            #pragma unroll
            for (int mt = 0; mt < 2; ++mt)
                #pragma unroll
                for (int nt = 0; nt < 4; ++nt) {
                    const uint32_t* Bh = &bh[nt >> 1][(nt & 1) * 2];
                    const uint32_t* Bl = &bl[nt >> 1][(nt & 1) * 2];
                    mma_bf16(acc[mt][nt], ah[mt], Bh);
                    mma_bf16(acc[mt][nt], ah[mt], Bl);
                    mma_bf16(acc[mt][nt], al[mt], Bh);
                }
        }
    };

    cp_wait<1>();
    __syncthreads();
    mma_range(0, KH);
    cp_wait<0>();
    __syncthreads();
    mma_range(KH, KSTEPS);

    #pragma unroll
    for (int mt = 0; mt < 2; ++mt)
        #pragma unroll
        for (int h = 0; h < 2; ++h) {
            const int rl = wm + mt * 16 + h * 8 + (lane >> 2);
            if (tilestart + rl >= tot) continue;
            const int dst = __ldg(&pairdst[q0 + rl]);
            float* out = g_contrib + (size_t)dst * 64;
            #pragma unroll
            for (int nt = 0; nt < 4; ++nt) {
                const int col = wn + nt * 8 + (lane & 3) * 2;
                float2 v;
                v.x = acc[mt][nt][h * 2];
                v.y = acc[mt][nt][h * 2 + 1];
                *(float2*)(out + col) = v;
            }
        }
}

// ---------------------------------------------------------------------------
// conv1 reduce: per-row contributions (contiguous, ascending-tap order)
// ---------------------------------------------------------------------------
__global__ __launch_bounds__(256) void reduce1_kernel(
    const float* __restrict__ bias, int n, const int* __restrict__ maskp,
    __nv_bfloat16* __restrict__ o_hi, __nv_bfloat16* __restrict__ o_lo)
{
    const int row = blockIdx.x * 8 + (threadIdx.x >> 5);
    if (row >= n) return;
    const int lane = threadIdx.x & 31;
    const int cnt  = __popc((unsigned)maskp[row]);
    const int c0   = lane * 2;
    const float* src = g_contrib + ((size_t)row << 5) * 64 + c0;
    float s0 = __ldg(&bias[c0]), s1 = __ldg(&bias[c0 + 1]);
    for (int j = 0; j < cnt; ++j) {
        const float2 v = *(const float2*)(src + (size_t)j * 64);
        s0 += v.x; s1 += v.y;
    }
    s0 = s0 >= 0.f ? s0 : 0.1f * s0;
    s1 = s1 >= 0.f ? s1 : 0.1f * s1;
    __nv_bfloat162 hh, ll;
    hh.x = __float2bfloat16_rn(s0);
    hh.y = __float2bfloat16_rn(s1);
    ll.x = __float2bfloat16_rn(s0 - __bfloat162float(hh.x));
    ll.y = __float2bfloat16_rn(s1 - __bfloat162float(hh.y));
    *(uint32_t*)(o_hi + (size_t)row * 64 + c0) = *(uint32_t*)&hh;
    *(uint32_t*)(o_lo + (size_t)row * 64 + c0) = *(uint32_t*)&ll;
}

// ---------------------------------------------------------------------------
// conv2 reduce + fused BN partials: writes f2 AND per-block sums/sumsqs
// ---------------------------------------------------------------------------
__global__ __launch_bounds__(256) void reduce2_bn_kernel(
    const float* __restrict__ bias, int n, const int* __restrict__ maskp,
    __nv_bfloat16* __restrict__ o_hi, __nv_bfloat16* __restrict__ o_lo,
    float* __restrict__ bnpart)
{
    const int w = threadIdx.x >> 5, lane = threadIdx.x & 31;
    const int row = blockIdx.x * 8 + w;
    const int c0 = lane * 2;

    float s0 = 0.f, s1 = 0.f;
    if (row < n) {
        const int cnt = __popc((unsigned)maskp[row]);
        const float* src = g_contrib + ((size_t)row << 3) * 64 + c0;
        s0 = __ldg(&bias[c0]); s1 = __ldg(&bias[c0 + 1]);
        for (int j = 0; j < cnt; ++j) {
            const float2 v = *(const float2*)(src + (size_t)j * 64);
            s0 += v.x; s1 += v.y;
        }
        s0 = s0 >= 0.f ? s0 : 0.1f * s0;
        s1 = s1 >= 0.f ? s1 : 0.1f * s1;
        __nv_bfloat162 hh, ll;
        hh.x = __float2bfloat16_rn(s0);
        hh.y = __float2bfloat16_rn(s1);
        ll.x = __float2bfloat16_rn(s0 - __bfloat162float(hh.x));
        ll.y = __float2bfloat16_rn(s1 - __bfloat162float(hh.y));
        *(uint32_t*)(o_hi + (size_t)row * 64 + c0) = *(uint32_t*)&hh;
        *(uint32_t*)(o_lo + (size_t)row * 64 + c0) = *(uint32_t*)&ll;
    }

    // per-block BN partials (fixed order over 8 warps -> deterministic)
    __shared__ float shs[8][64], shq[8][64];
    shs[w][c0]     = s0; shs[w][c0 + 1] = s1;
    shq[w][c0]     = s0 * s0; shq[w][c0 + 1] = s1 * s1;
    __syncthreads();
    if (threadIdx.x < 64) {
        const int c = threadIdx.x;
        float a = 0.f, b = 0.f;
        #pragma unroll
        for (int i = 0; i < 8; ++i) { a += shs[i][c]; b += shq[i][c]; }
        bnpart[blockIdx.x * 128 + c]      = a;
        bnpart[blockIdx.x * 128 + 64 + c] = b;
    }
}

// finalize: sum block partials, compute st scale/shift
__global__ void bn_finalize2_kernel(
    const float* __restrict__ bnpart, int G, int n2,
    const float* __restrict__ gamma, const float* __restrict__ beta,
    const float* __restrict__ scale, float* __restrict__ st)
{
    __shared__ float tot[128];
    const int t = threadIdx.x;           // 128 threads
    float s = 0.f;
    #pragma unroll 4
    for (int g = 0; g < G; ++g) s += bnpart[g * 128 + t];
    tot[t] = s;
    __syncthreads();
    if (t < 64) {
        const float inv_n = 1.0f / (float)n2;
        const float mu  = tot[t] * inv_n;
        const float var = fmaxf(tot[64 + t] * inv_n - mu * mu, 0.f);
        const float r   = rsqrtf(var + 1e-5f);
        const float sc  = scale[0];
        st[t]      = gamma[t] * r * sc;
        st[64 + t] = (beta[t] - mu * gamma[t] * r) * sc;
    }
}

__global__ __launch_bounds__(256) void bn_apply_kernel(
    __nv_bfloat16* __restrict__ fh, __nv_bfloat16* __restrict__ fl,
    int n2, const float* __restrict__ st)
{
    const int i = blockIdx.x * 256 + threadIdx.x;
    if (i < n2 * 64) {
        const int c = i & 63;
        const float v = fmaf(__bfloat162float(fh[i]) + __bfloat162float(fl[i]),
                             st[c], st[64 + c]);
        const __nv_bfloat16 h = __float2bfloat16_rn(v);
        fh[i] = h;
        fl[i] = __float2bfloat16_rn(v - __bfloat162float(h));
    }
}

// ===========================================================================
// Dense gather-GEMM (conv3): 2-stage cp.async pipeline, 8 warps (4x2)
// ===========================================================================
template <int CIN, int KT>
__global__ __launch_bounds__(256) void sconv_dense(
    const __nv_bfloat16* __restrict__ a_hi, const __nv_bfloat16* __restrict__ a_lo,
    int n_in, const int* __restrict__ nmap, int n_out,
    const __nv_bfloat16* __restrict__ w_hi, const __nv_bfloat16* __restrict__ w_lo,
    const float* __restrict__ bias, float* __restrict__ o_f32)
{
    constexpr int LDA = CIN + 8;
    constexpr int LDB = 72;
    constexpr int KSTEPS = CIN / 16;
    constexpr int CPR = CIN / 8;
    constexpr int A_HALVES = 128 * LDA;
    constexpr int B_HALVES = CIN * LDB;
    constexpr uint32_t OFF_ALO = (uint32_t)A_HALVES * 2;
    constexpr uint32_t OFF_BHI = (uint32_t)(2 * A_HALVES) * 2;
    constexpr uint32_t OFF_BLO = (uint32_t)(2 * A_HALVES + B_HALVES) * 2;
    constexpr uint32_t STAGE   = (uint32_t)(2 * A_HALVES + 2 * B_HALVES) * 2;

    extern __shared__ __align__(16) __nv_bfloat16 smem[];
    const uint32_t sb = smem_u32(smem);

    const int tid  = threadIdx.x;
    const int wid  = tid >> 5;
    const int lane = tid & 31;
    const int row0 = blockIdx.x * 128;
    const int wm   = (wid >> 1) * 32;
    const int wn   = (wid & 1) * 32;
    const int lrow = lane & 15, lcol8 = (lane >> 4) * 8;

    float acc[2][4][4] = {};

    auto prefetch = [&](int t, uint32_t stoff) {
        #pragma unroll 2
        for (int i = tid; i < 2 * 128 * CPR; i += 256) {
            const int buf = i / (128 * CPR);
            const int j   = i % (128 * CPR);
            const int r   = j / CPR, c = j % CPR;
            const int rr  = row0 + r;
            int idx = n_in;
            if (rr < n_out) idx = __ldg(&nmap[(size_t)rr * KT + t]);
            const int ok = idx < n_in;
            const __nv_bfloat16* src = (buf ? a_lo : a_hi)
                + (size_t)(ok ? idx : 0) * CIN + c * 8;
            cp16(sb + stoff + (buf ? OFF_ALO : 0u)
                 + (uint32_t)(r * LDA + c * 8) * 2, src, ok ? 16 : 0);
        }
        #pragma unroll 2
        for (int i = tid; i < 2 * CIN * 8; i += 256) {
            const int buf = i / (CIN * 8);
            const int j   = i % (CIN * 8);
            const int r   = j >> 3, c = j & 7;
            const __nv_bfloat16* src = (buf ? w_lo : w_hi)
                + (size_t)t * CIN * 64 + r * 64 + c * 8;
            cp16(sb + stoff + (buf ? OFF_BLO : OFF_BHI)
                 + (uint32_t)(r * LDB + c * 8) * 2, src, 16);
        }
    };

    prefetch(0, 0);
    cp_commit();

    for (int t = 0; t < KT; ++t) {
        const uint32_t stoff = (t & 1) ? STAGE : 0u;
        if (t + 1 < KT) {
            prefetch(t + 1, (t & 1) ? 0u : STAGE);
            cp_commit();
            cp_wait<1>();
        } else {
            cp_wait<0>();
        }
        __syncthreads();

        #pragma unroll
        for (int s = 0; s < KSTEPS; ++s) {
            uint32_t ah[2][4], al[2][4];
            #pragma unroll
            for (int mt = 0; mt < 2; ++mt) {
                const uint32_t off = (uint32_t)((wm + mt * 16 + lrow) * LDA
                                                + s * 16 + lcol8) * 2;
                ldsm_x4(ah[mt], sb + stoff + off);
                ldsm_x4(al[mt], sb + stoff + OFF_ALO + off);
            }
            uint32_t bh[2][4], bl[2][4];
            #pragma unroll
            for (int p = 0; p < 2; ++p) {
                const uint32_t off = (uint32_t)((s * 16 + lrow) * LDB
                                                + wn + p * 16 + lcol8) * 2;
                ldsm_x4_t(bh[p], sb + stoff + OFF_BHI + off);
                ldsm_x4_t(bl[p], sb + stoff + OFF_BLO + off);
            }
            #pragma unroll
            for (int mt = 0; mt < 2; ++mt)
                #pragma unroll
                for (int nt = 0; nt < 4; ++nt) {
                    const uint32_t* Bh = &bh[nt >> 1][(nt & 1) * 2];
                    const uint32_t* Bl = &bl[nt >> 1][(nt & 1) * 2];
                    mma_bf16(acc[mt][nt], ah[mt], Bh);
                    mma_bf16(acc[mt][nt], ah[mt], Bl);
                    mma_bf16(acc[mt][nt], al[mt], Bh);
                }
        }
        __syncthreads();
    }

    #pragma unroll
    for (int mt = 0; mt < 2; ++mt)
        #pragma unroll
        for (int nt = 0; nt < 4; ++nt)
            #pragma unroll
            for (int h = 0; h < 2; ++h) {
                const int row = row0 + wm + mt * 16 + h * 8 + (lane >> 2);
                if (row >= n_out) continue;
                const int col = wn + nt * 8 + (lane & 3) * 2;
                float2 v;
                v.x = acc[mt][nt][h * 2]     + __ldg(&bias[col]);
                v.y = acc[mt][nt][h * 2 + 1] + __ldg(&bias[col + 1]);
                *(float2*)(o_f32 + (size_t)row * 64 + col) = v;
            }
}

// ---------------------------------------------------------------------------
// Merged split: x | W1 | W2 | W3 -> bf16 hi/lo.  Also zeroes tap counters.
// ---------------------------------------------------------------------------
__global__ __launch_bounds__(256) void splitall_kernel(
    const float* __restrict__ x, __nv_bfloat16* __restrict__ xh, __nv_bfloat16* __restrict__ xl, int nx,
    const float* __restrict__ W1, __nv_bfloat16* __restrict__ h1, __nv_bfloat16* __restrict__ l1, int n1,
    const float* __restrict__ W2, __nv_bfloat16* __restrict__ h2, __nv_bfloat16* __restrict__ l2, int n2,
    const float* __restrict__ W3, __nv_bfloat16* __restrict__ h3, __nv_bfloat16* __restrict__ l3, int n3)
{
    if (blockIdx.x == 0) {
        if (threadIdx.x < KT1) g_tapcnt1[threadIdx.x] = 0;
        else if (threadIdx.x < KT1 + KT2) g_tapcnt2[threadIdx.x - KT1] = 0;
    }
    const int total = nx + n1 + n2 + n3;
    for (int i = blockIdx.x * 256 + threadIdx.x; i < total; i += gridDim.x * 256) {
        const float* s; __nv_bfloat16 *hp, *lp; int j;
        if (i < nx)                { s = x;  hp = xh; lp = xl; j = i; }
        else if (i < nx + n1)      { s = W1; hp = h1; lp = l1; j = i - nx; }
        else if (i < nx + n1 + n2) { s = W2; hp = h2; lp = l2; j = i - nx - n1; }
        else                       { s = W3; hp = h3; lp = l3; j = i - nx - n1 - n2; }
        const float v = s[j];
        const __nv_bfloat16 h = __float2bfloat16_rn(v);
        hp[j] = h;
        lp[j] = __float2bfloat16_rn(v - __bfloat162float(h));
    }
}

// ---------------------------------------------------------------------------
extern "C" void kernel_launch(void* const* d_in, const int* in_sizes, int n_in_arrs,
                              void* d_out, int out_size)
{
    const float* x     = (const float*)d_in[0];
    const float* W1    = (const float*)d_in[1];
    const float* b1    = (const float*)d_in[2];
    const float* W2    = (const float*)d_in[3];
    const float* b2    = (const float*)d_in[4];
    const float* W3    = (const float*)d_in[5];
    const float* b3    = (const float*)d_in[6];
    const float* gamma = (const float*)d_in[7];
    const float* beta  = (const float*)d_in[8];
    const float* scale = (const float*)d_in[9];
    const int* nmap1   = (const int*)d_in[10];
    const int* nmap2   = (const int*)d_in[11];
    const int* nmap3   = (const int*)d_in[12];

    const int N    = in_sizes[0] / 96;
    const int N2   = in_sizes[11] / 8;
    const int NB   = (N + 255) / 256;
    const int NB2  = (N2 + 255) / 256;
    const int NRB2 = (N2 + 7) / 8;           // reduce2 blocks = BN partial groups

    __nv_bfloat16 *xh, *xl, *f1h, *f1l, *f2h, *f2l, *w1h, *w1l, *w2h, *w2l, *w3h, *w3l;
    float *st, *bnpart;
    int *mask1, *mask2, *tapcnt1, *tapcnt2, *pi1, *pd1, *pi2, *pd2;
    cudaGetSymbolAddress((void**)&xh, g_x_hi);   cudaGetSymbolAddress((void**)&xl, g_x_lo);
    cudaGetSymbolAddress((void**)&f1h, g_f1_hi); cudaGetSymbolAddress((void**)&f1l, g_f1_lo);
    cudaGetSymbolAddress((void**)&f2h, g_f2_hi); cudaGetSymbolAddress((void**)&f2l, g_f2_lo);
    cudaGetSymbolAddress((void**)&w1h, g_w1_hi); cudaGetSymbolAddress((void**)&w1l, g_w1_lo);
    cudaGetSymbolAddress((void**)&w2h, g_w2_hi); cudaGetSymbolAddress((void**)&w2l, g_w2_lo);
    cudaGetSymbolAddress((void**)&w3h, g_w3_hi); cudaGetSymbolAddress((void**)&w3l, g_w3_lo);
    cudaGetSymbolAddress((void**)&st, g_st);
    cudaGetSymbolAddress((void**)&bnpart, g_bnpart);
    cudaGetSymbolAddress((void**)&mask1, g_mask1);
    cudaGetSymbolAddress((void**)&mask2, g_mask2);
    cudaGetSymbolAddress((void**)&tapcnt1, g_tapcnt1);
    cudaGetSymbolAddress((void**)&tapcnt2, g_tapcnt2);
    cudaGetSymbolAddress((void**)&pi1, g_pairidx1);
    cudaGetSymbolAddress((void**)&pd1, g_pairdst1);
    cudaGetSymbolAddress((void**)&pi2, g_pairidx2);
    cudaGetSymbolAddress((void**)&pd2, g_pairdst2);

    // prep: merged split (also zeroes both tap counter arrays)
    splitall_kernel<<<512, 256>>>(x, xh, xl, N * 96,
                                  W1, w1h, w1l, 27 * 96 * 64,
                                  W2, w2h, w2l, 8 * 64 * 64,
                                  W3, w3h, w3l, 27 * 64 * 64);

    // ---- compaction preps ----
    emit_fused<KT1, 5><<<NB,  256>>>(nmap1, N,  N, mask1, tapcnt1, pi1, pd1);
    emit_fused<KT2, 3><<<NB2, 256>>>(nmap2, N2, N, mask2, tapcnt2, pi2, pd2);

    // ---- conv1: compacted (27 taps, 96ch), swizzled, 3 CTAs/SM ----
    {
        constexpr int smem = (2 * 128 * 96 + 2 * 96 * 64) * 2;    // 73,728 B
        cudaFuncSetAttribute(conv_compact<96>,
                             cudaFuncAttributeMaxDynamicSharedMemorySize, smem);
        dim3 grid((N + 127) / 128, KT1);
        conv_compact<96><<<grid, 256, smem>>>(xh, xl, w1h, w1l, tapcnt1, pi1, pd1);
    }
    reduce1_kernel<<<(N + 7) / 8, 256>>>(b1, N, mask1, f1h, f1l);

    // ---- conv2: compacted (8 taps, 64ch), swizzled; reduce fuses BN stats ----
    {
        constexpr int smem = (2 * 128 * 64 + 2 * 64 * 64) * 2;    // 49,152 B
        cudaFuncSetAttribute(conv_compact<64>,
                             cudaFuncAttributeMaxDynamicSharedMemorySize, smem);
        dim3 grid((N2 + 127) / 128, KT2);
        conv_compact<64><<<grid, 256, smem>>>(f1h, f1l, w2h, w2l, tapcnt2, pi2, pd2);
    }
    reduce2_bn_kernel<<<NRB2, 256>>>(b2, N2, mask2, f2h, f2l, bnpart);

    // ---- batch norm finalize + apply ----
    bn_finalize2_kernel<<<1, 128>>>(bnpart, NRB2, N2, gamma, beta, scale, st);
    bn_apply_kernel<<<(N2 * 64 + 255) / 256, 256>>>(f2h, f2l, N2, st);

    // ---- conv3: dense, 27 taps, fp32 out ----
    {
        constexpr int stage = (2 * 128 * 72 + 2 * 64 * 72) * 2;
        constexpr int smem  = 2 * stage;                          // 110,592 B
        cudaFuncSetAttribute(sconv_dense<64, 27>,
                             cudaFuncAttributeMaxDynamicSharedMemorySize, smem);
        sconv_dense<64, 27><<<(N2 + 127) / 128, 256, smem>>>(
            f2h, f2l, N2, nmap3, N2, w3h, w3l, b3, (float*)d_out);
    }
}

// round 17
// speedup vs baseline: 2.0241x; 2.0241x over previous
#include <cuda_runtime.h>
#include <cuda_bf16.h>
#include <cstdint>

// ===========================================================================
// Sparse conv encoder, mma.sync bf16 hi/lo x3.
// conv1/conv2: per-tap COMPACTED gather-GEMM (swizzled smem, 3 CTAs/SM,
//   split-gather pipeline, fused atomic-emit prep, scatter/stream contrib).
// conv3: dense cp.async pipeline (R14 form).
// R17: BN stats fused into conv2 reduce; finalize now TWO-STAGE PARALLEL
//   (R16's single-block serial finalize was a ~200us latency bomb).
// ===========================================================================

#define MAXN 60032
#define KT1 27
#define KT2 8

__device__ __nv_bfloat16 g_x_hi[MAXN * 96];
__device__ __nv_bfloat16 g_x_lo[MAXN * 96];
__device__ __nv_bfloat16 g_f1_hi[MAXN * 64];
__device__ __nv_bfloat16 g_f1_lo[MAXN * 64];
__device__ __nv_bfloat16 g_f2_hi[MAXN * 64];
__device__ __nv_bfloat16 g_f2_lo[MAXN * 64];
__device__ __nv_bfloat16 g_w1_hi[27 * 96 * 64];
__device__ __nv_bfloat16 g_w1_lo[27 * 96 * 64];
__device__ __nv_bfloat16 g_w2_hi[8 * 64 * 64];
__device__ __nv_bfloat16 g_w2_lo[8 * 64 * 64];
__device__ __nv_bfloat16 g_w3_hi[27 * 64 * 64];
__device__ __nv_bfloat16 g_w3_lo[27 * 64 * 64];
__device__ float g_st[128];
__device__ float g_bntot[128];
__device__ float g_bnpart[7552 * 128];           // per-block BN partials

// compaction structures
__device__ int   g_mask1[MAXN];
__device__ int   g_mask2[MAXN];
__device__ int   g_tapcnt1[KT1];
__device__ int   g_tapcnt2[KT2];
__device__ int   g_pairidx1[KT1 * MAXN];
__device__ int   g_pairdst1[KT1 * MAXN];         // (row<<5)|j
__device__ int   g_pairidx2[KT2 * MAXN];
__device__ int   g_pairdst2[KT2 * MAXN];         // (row<<3)|j
__device__ float g_contrib[(size_t)MAXN * 32 * 64];

__device__ __forceinline__ uint32_t smem_u32(const void* p) {
    uint32_t a;
    asm("{ .reg .u64 t; cvta.to.shared.u64 t, %1; cvt.u32.u64 %0, t; }"
        : "=r"(a) : "l"(p));
    return a;
}
__device__ __forceinline__ void cp16(uint32_t s, const void* g, int sz) {
    asm volatile("cp.async.cg.shared.global [%0], [%1], 16, %2;"
                 :: "r"(s), "l"(g), "r"(sz) : "memory");
}
__device__ __forceinline__ void cp_commit() {
    asm volatile("cp.async.commit_group;" ::: "memory");
}
template <int N>
__device__ __forceinline__ void cp_wait() {
    asm volatile("cp.async.wait_group %0;" :: "n"(N) : "memory");
}
__device__ __forceinline__ void ldsm_x4(uint32_t* r, uint32_t addr) {
    asm volatile("ldmatrix.sync.aligned.m8n8.x4.shared.b16 {%0,%1,%2,%3}, [%4];"
                 : "=r"(r[0]), "=r"(r[1]), "=r"(r[2]), "=r"(r[3]) : "r"(addr));
}
__device__ __forceinline__ void ldsm_x4_t(uint32_t* r, uint32_t addr) {
    asm volatile("ldmatrix.sync.aligned.m8n8.x4.trans.shared.b16 {%0,%1,%2,%3}, [%4];"
                 : "=r"(r[0]), "=r"(r[1]), "=r"(r[2]), "=r"(r[3]) : "r"(addr));
}
__device__ __forceinline__ void mma_bf16(float* d, const uint32_t* a, const uint32_t* b) {
    asm volatile(
        "mma.sync.aligned.m16n8k16.row.col.f32.bf16.bf16.f32 "
        "{%0,%1,%2,%3}, {%4,%5,%6,%7}, {%8,%9}, {%0,%1,%2,%3};"
        : "+f"(d[0]), "+f"(d[1]), "+f"(d[2]), "+f"(d[3])
        : "r"(a[0]), "r"(a[1]), "r"(a[2]), "r"(a[3]), "r"(b[0]), "r"(b[1]));
}

// 16B-chunk XOR swizzles (same formula for cp.async write and ldmatrix read)
template <int CIN>
__device__ __forceinline__ int swzA(int c, int r) {
    return (CIN == 96) ? (c ^ ((r >> 1) & 3)) : (c ^ (r & 7));
}
__device__ __forceinline__ int swzB(int c, int r) { return c ^ (r & 7); }

// ===========================================================================
// Fused compaction (templated): mask + block histogram + atomic base + emit.
// ===========================================================================
template <int KT, int SHIFT>
__global__ __launch_bounds__(256) void emit_fused(
    const int* __restrict__ nmap, int n, int n_in,
    int* __restrict__ maskp, int* __restrict__ tapcnt,
    int* __restrict__ pairidx, int* __restrict__ pairdst)
{
    const int t = threadIdx.x, lane = t & 31, w = t >> 5;
    const int row = blockIdx.x * 256 + t;

    int idxs[KT];
    unsigned m = 0;
    if (row < n) {
        #pragma unroll
        for (int k = 0; k < KT; ++k) {
            idxs[k] = __ldg(&nmap[(size_t)row * KT + k]);
            if (idxs[k] < n_in) m |= 1u << k;
        }
        maskp[row] = (int)m;
    }

    __shared__ int hist[KT], base[KT], wt[KT][8];
    if (t < KT) hist[t] = 0;
    __syncthreads();
    #pragma unroll
    for (int k = 0; k < KT; ++k) {
        const unsigned bal = __ballot_sync(0xffffffffu, (m >> k) & 1);
        if (lane == 0) { wt[k][w] = __popc(bal); if (bal) atomicAdd(&hist[k], __popc(bal)); }
    }
    __syncthreads();
    if (t < KT) base[t] = atomicAdd(&tapcnt[t], hist[t]);
    __syncthreads();

    int j = 0;
    #pragma unroll
    for (int k = 0; k < KT; ++k) {
        const int valid = (m >> k) & 1;
        const unsigned bal = __ballot_sync(0xffffffffu, valid);
        if (valid) {
            int wb = 0;
            #pragma unroll
            for (int i = 0; i < 8; ++i) if (i < w) wb += wt[k][i];
            const int rank = wb + __popc(bal & ((1u << lane) - 1u));
            const int pos  = k * MAXN + base[k] + rank;
            pairidx[pos] = idxs[k];
            pairdst[pos] = (row << SHIFT) | j;
            ++j;
        }
    }
}

// ===========================================================================
// Compact GEMM, swizzled smem, split-gather pipeline (R14 config).
// ===========================================================================
template <int CIN>
__global__ __launch_bounds__(256, 3) void conv_compact(
    const __nv_bfloat16* __restrict__ a_hi, const __nv_bfloat16* __restrict__ a_lo,
    const __nv_bfloat16* __restrict__ w_hi, const __nv_bfloat16* __restrict__ w_lo,
    const int* __restrict__ tapcnt,
    const int* __restrict__ pairidx, const int* __restrict__ pairdst)
{
    constexpr int KSTEPS = CIN / 16;
    constexpr int KH = KSTEPS / 2;
    constexpr int CPR = CIN / 8;
    constexpr int CPRH = CPR / 2;
    constexpr uint32_t OFF_ALO = (uint32_t)(128 * CIN) * 2;
    constexpr uint32_t OFF_BHI = 2 * OFF_ALO;
    constexpr uint32_t OFF_BLO = OFF_BHI + (uint32_t)(CIN * 64) * 2;

    const int k = blockIdx.y;
    const int tot = __ldg(&tapcnt[k]);
    const int tilestart = blockIdx.x * 128;
    if (tilestart >= tot) return;
    const int q0 = k * MAXN + tilestart;

    extern __shared__ __align__(16) __nv_bfloat16 smem[];
    const uint32_t sb = smem_u32(smem);
    const int tid = threadIdx.x, wid = tid >> 5, lane = tid & 31;
    const int wm = (wid >> 1) * 32, wn = (wid & 1) * 32;
    const int lrow = lane & 15, lhalf = lane >> 4;

    #pragma unroll 2
    for (int i = tid; i < 2 * 128 * CPRH; i += 256) {
        const int buf = i / (128 * CPRH);
        const int j   = i % (128 * CPRH);
        const int r   = j / CPRH, c = j % CPRH;
        const int ok  = tilestart + r < tot;
        const int idx = ok ? __ldg(&pairidx[q0 + r]) : 0;
        const __nv_bfloat16* src = (buf ? a_lo : a_hi) + (size_t)idx * CIN + c * 8;
        cp16(sb + (buf ? OFF_ALO : 0u)
             + (uint32_t)(r * CPR + swzA<CIN>(c, r)) * 16, src, ok ? 16 : 0);
    }
    #pragma unroll 2
    for (int i = tid; i < 2 * CIN * 8; i += 256) {
        const int buf = i / (CIN * 8);
        const int j   = i % (CIN * 8);
        const int r   = j >> 3, c = j & 7;
        const __nv_bfloat16* src = (buf ? w_lo : w_hi)
            + (size_t)k * CIN * 64 + r * 64 + c * 8;
        cp16(sb + (buf ? OFF_BLO : OFF_BHI)
             + (uint32_t)(r * 8 + swzB(c, r)) * 16, src, 16);
    }
    cp_commit();

    #pragma unroll 2
    for (int i = tid; i < 2 * 128 * CPRH; i += 256) {
        const int buf = i / (128 * CPRH);
        const int j   = i % (128 * CPRH);
        const int r   = j / CPRH, c = j % CPRH + CPRH;
        const int ok  = tilestart + r < tot;
        const int idx = ok ? __ldg(&pairidx[q0 + r]) : 0;
        const __nv_bfloat16* src = (buf ? a_lo : a_hi) + (size_t)idx * CIN + c * 8;
        cp16(sb + (buf ? OFF_ALO : 0u)
             + (uint32_t)(r * CPR + swzA<CIN>(c, r)) * 16, src, ok ? 16 : 0);
    }
    cp_commit();

    float acc[2][4][4] = {};

    auto mma_range = [&](int s0, int s1) {
        for (int s = s0; s < s1; ++s) {
            uint32_t ah[2][4], al[2][4];
            #pragma unroll
            for (int mt = 0; mt < 2; ++mt) {
                const int row = wm + mt * 16 + lrow;
                const uint32_t off =
                    (uint32_t)(row * CPR + swzA<CIN>(2 * s + lhalf, row)) * 16;
                ldsm_x4(ah[mt], sb + off);
                ldsm_x4(al[mt], sb + OFF_ALO + off);
            }
            uint32_t bh[2][4], bl[2][4];
            #pragma unroll
            for (int p = 0; p < 2; ++p) {
                const int rk = s * 16 + lrow;
                const int cb = (wn >> 3) + 2 * p + lhalf;
                const uint32_t off = (uint32_t)(rk * 8 + swzB(cb, rk)) * 16;
                ldsm_x4_t(bh[p], sb + OFF_BHI + off);
                ldsm_x4_t(bl[p], sb + OFF_BLO + off);
            }
            #pragma unroll
            for (int mt = 0; mt < 2; ++mt)
                #pragma unroll
                for (int nt = 0; nt < 4; ++nt) {
                    const uint32_t* Bh = &bh[nt >> 1][(nt & 1) * 2];
                    const uint32_t* Bl = &bl[nt >> 1][(nt & 1) * 2];
                    mma_bf16(acc[mt][nt], ah[mt], Bh);
                    mma_bf16(acc[mt][nt], ah[mt], Bl);
                    mma_bf16(acc[mt][nt], al[mt], Bh);
                }
        }
    };

    cp_wait<1>();
    __syncthreads();
    mma_range(0, KH);
    cp_wait<0>();
    __syncthreads();
    mma_range(KH, KSTEPS);

    #pragma unroll
    for (int mt = 0; mt < 2; ++mt)
        #pragma unroll
        for (int h = 0; h < 2; ++h) {
            const int rl = wm + mt * 16 + h * 8 + (lane >> 2);
            if (tilestart + rl >= tot) continue;
            const int dst = __ldg(&pairdst[q0 + rl]);
            float* out = g_contrib + (size_t)dst * 64;
            #pragma unroll
            for (int nt = 0; nt < 4; ++nt) {
                const int col = wn + nt * 8 + (lane & 3) * 2;
                float2 v;
                v.x = acc[mt][nt][h * 2];
                v.y = acc[mt][nt][h * 2 + 1];
                *(float2*)(out + col) = v;
            }
        }
}

// ---------------------------------------------------------------------------
// conv1 reduce: per-row contributions (contiguous, ascending-tap order)
// ---------------------------------------------------------------------------
__global__ __launch_bounds__(256) void reduce1_kernel(
    const float* __restrict__ bias, int n, const int* __restrict__ maskp,
    __nv_bfloat16* __restrict__ o_hi, __nv_bfloat16* __restrict__ o_lo)
{
    const int row = blockIdx.x * 8 + (threadIdx.x >> 5);
    if (row >= n) return;
    const int lane = threadIdx.x & 31;
    const int cnt  = __popc((unsigned)maskp[row]);
    const int c0   = lane * 2;
    const float* src = g_contrib + ((size_t)row << 5) * 64 + c0;
    float s0 = __ldg(&bias[c0]), s1 = __ldg(&bias[c0 + 1]);
    for (int j = 0; j < cnt; ++j) {
        const float2 v = *(const float2*)(src + (size_t)j * 64);
        s0 += v.x; s1 += v.y;
    }
    s0 = s0 >= 0.f ? s0 : 0.1f * s0;
    s1 = s1 >= 0.f ? s1 : 0.1f * s1;
    __nv_bfloat162 hh, ll;
    hh.x = __float2bfloat16_rn(s0);
    hh.y = __float2bfloat16_rn(s1);
    ll.x = __float2bfloat16_rn(s0 - __bfloat162float(hh.x));
    ll.y = __float2bfloat16_rn(s1 - __bfloat162float(hh.y));
    *(uint32_t*)(o_hi + (size_t)row * 64 + c0) = *(uint32_t*)&hh;
    *(uint32_t*)(o_lo + (size_t)row * 64 + c0) = *(uint32_t*)&ll;
}

// ---------------------------------------------------------------------------
// conv2 reduce + fused BN partials: writes f2 AND per-block sums/sumsqs
// ---------------------------------------------------------------------------
__global__ __launch_bounds__(256) void reduce2_bn_kernel(
    const float* __restrict__ bias, int n, const int* __restrict__ maskp,
    __nv_bfloat16* __restrict__ o_hi, __nv_bfloat16* __restrict__ o_lo,
    float* __restrict__ bnpart)
{
    const int w = threadIdx.x >> 5, lane = threadIdx.x & 31;
    const int row = blockIdx.x * 8 + w;
    const int c0 = lane * 2;

    float s0 = 0.f, s1 = 0.f;
    if (row < n) {
        const int cnt = __popc((unsigned)maskp[row]);
        const float* src = g_contrib + ((size_t)row << 3) * 64 + c0;
        s0 = __ldg(&bias[c0]); s1 = __ldg(&bias[c0 + 1]);
        for (int j = 0; j < cnt; ++j) {
            const float2 v = *(const float2*)(src + (size_t)j * 64);
            s0 += v.x; s1 += v.y;
        }
        s0 = s0 >= 0.f ? s0 : 0.1f * s0;
        s1 = s1 >= 0.f ? s1 : 0.1f * s1;
        __nv_bfloat162 hh, ll;
        hh.x = __float2bfloat16_rn(s0);
        hh.y = __float2bfloat16_rn(s1);
        ll.x = __float2bfloat16_rn(s0 - __bfloat162float(hh.x));
        ll.y = __float2bfloat16_rn(s1 - __bfloat162float(hh.y));
        *(uint32_t*)(o_hi + (size_t)row * 64 + c0) = *(uint32_t*)&hh;
        *(uint32_t*)(o_lo + (size_t)row * 64 + c0) = *(uint32_t*)&ll;
    }

    // per-block BN partials (fixed order over 8 warps -> deterministic)
    __shared__ float shs[8][64], shq[8][64];
    shs[w][c0]     = s0; shs[w][c0 + 1] = s1;
    shq[w][c0]     = s0 * s0; shq[w][c0 + 1] = s1 * s1;
    __syncthreads();
    if (threadIdx.x < 64) {
        const int c = threadIdx.x;
        float a = 0.f, b = 0.f;
        #pragma unroll
        for (int i = 0; i < 8; ++i) { a += shs[i][c]; b += shq[i][c]; }
        bnpart[blockIdx.x * 128 + c]      = a;
        bnpart[blockIdx.x * 128 + 64 + c] = b;
    }
}

// ---------------------------------------------------------------------------
// BN finalize, stage 1: 128 blocks, one per stat column; parallel strided sum
// ---------------------------------------------------------------------------
__global__ __launch_bounds__(256) void bn_sum_kernel(
    const float* __restrict__ bnpart, int G, float* __restrict__ tot)
{
    const int col = blockIdx.x;                    // 0..127
    float s = 0.f;
    for (int g = threadIdx.x; g < G; g += 256)
        s += bnpart[(size_t)g * 128 + col];
    __shared__ float sh[256];
    sh[threadIdx.x] = s;
    __syncthreads();
    #pragma unroll
    for (int o = 128; o > 0; o >>= 1) {
        if (threadIdx.x < o) sh[threadIdx.x] += sh[threadIdx.x + o];
        __syncthreads();
    }
    if (threadIdx.x == 0) tot[col] = sh[0];
}

// BN finalize, stage 2: compute st scale/shift from 128 totals
__global__ void bn_st_kernel(
    const float* __restrict__ tot, int n2,
    const float* __restrict__ gamma, const float* __restrict__ beta,
    const float* __restrict__ scale, float* __restrict__ st)
{
    const int c = threadIdx.x;                     // 64 threads
    const float inv_n = 1.0f / (float)n2;
    const float mu  = tot[c] * inv_n;
    const float var = fmaxf(tot[64 + c] * inv_n - mu * mu, 0.f);
    const float r   = rsqrtf(var + 1e-5f);
    const float sc  = scale[0];
    st[c]      = gamma[c] * r * sc;
    st[64 + c] = (beta[c] - mu * gamma[c] * r) * sc;
}

__global__ __launch_bounds__(256) void bn_apply_kernel(
    __nv_bfloat16* __restrict__ fh, __nv_bfloat16* __restrict__ fl,
    int n2, const float* __restrict__ st)
{
    const int i = blockIdx.x * 256 + threadIdx.x;
    if (i < n2 * 64) {
        const int c = i & 63;
        const float v = fmaf(__bfloat162float(fh[i]) + __bfloat162float(fl[i]),
                             st[c], st[64 + c]);
        const __nv_bfloat16 h = __float2bfloat16_rn(v);
        fh[i] = h;
        fl[i] = __float2bfloat16_rn(v - __bfloat162float(h));
    }
}

// ===========================================================================
// Dense gather-GEMM (conv3): 2-stage cp.async pipeline, 8 warps (4x2)
// ===========================================================================
template <int CIN, int KT>
__global__ __launch_bounds__(256) void sconv_dense(
    const __nv_bfloat16* __restrict__ a_hi, const __nv_bfloat16* __restrict__ a_lo,
    int n_in, const int* __restrict__ nmap, int n_out,
    const __nv_bfloat16* __restrict__ w_hi, const __nv_bfloat16* __restrict__ w_lo,
    const float* __restrict__ bias, float* __restrict__ o_f32)
{
    constexpr int LDA = CIN + 8;
    constexpr int LDB = 72;
    constexpr int KSTEPS = CIN / 16;
    constexpr int CPR = CIN / 8;
    constexpr int A_HALVES = 128 * LDA;
    constexpr int B_HALVES = CIN * LDB;
    constexpr uint32_t OFF_ALO = (uint32_t)A_HALVES * 2;
    constexpr uint32_t OFF_BHI = (uint32_t)(2 * A_HALVES) * 2;
    constexpr uint32_t OFF_BLO = (uint32_t)(2 * A_HALVES + B_HALVES) * 2;
    constexpr uint32_t STAGE   = (uint32_t)(2 * A_HALVES + 2 * B_HALVES) * 2;

    extern __shared__ __align__(16) __nv_bfloat16 smem[];
    const uint32_t sb = smem_u32(smem);

    const int tid  = threadIdx.x;
    const int wid  = tid >> 5;
    const int lane = tid & 31;
    const int row0 = blockIdx.x * 128;
    const int wm   = (wid >> 1) * 32;
    const int wn   = (wid & 1) * 32;
    const int lrow = lane & 15, lcol8 = (lane >> 4) * 8;

    float acc[2][4][4] = {};

    auto prefetch = [&](int t, uint32_t stoff) {
        #pragma unroll 2
        for (int i = tid; i < 2 * 128 * CPR; i += 256) {
            const int buf = i / (128 * CPR);
            const int j   = i % (128 * CPR);
            const int r   = j / CPR, c = j % CPR;
            const int rr  = row0 + r;
            int idx = n_in;
            if (rr < n_out) idx = __ldg(&nmap[(size_t)rr * KT + t]);
            const int ok = idx < n_in;
            const __nv_bfloat16* src = (buf ? a_lo : a_hi)
                + (size_t)(ok ? idx : 0) * CIN + c * 8;
            cp16(sb + stoff + (buf ? OFF_ALO : 0u)
                 + (uint32_t)(r * LDA + c * 8) * 2, src, ok ? 16 : 0);
        }
        #pragma unroll 2
        for (int i = tid; i < 2 * CIN * 8; i += 256) {
            const int buf = i / (CIN * 8);
            const int j   = i % (CIN * 8);
            const int r   = j >> 3, c = j & 7;
            const __nv_bfloat16* src = (buf ? w_lo : w_hi)
                + (size_t)t * CIN * 64 + r * 64 + c * 8;
            cp16(sb + stoff + (buf ? OFF_BLO : OFF_BHI)
                 + (uint32_t)(r * LDB + c * 8) * 2, src, 16);
        }
    };

    prefetch(0, 0);
    cp_commit();

    for (int t = 0; t < KT; ++t) {
        const uint32_t stoff = (t & 1) ? STAGE : 0u;
        if (t + 1 < KT) {
            prefetch(t + 1, (t & 1) ? 0u : STAGE);
            cp_commit();
            cp_wait<1>();
        } else {
            cp_wait<0>();
        }
        __syncthreads();

        #pragma unroll
        for (int s = 0; s < KSTEPS; ++s) {
            uint32_t ah[2][4], al[2][4];
            #pragma unroll
            for (int mt = 0; mt < 2; ++mt) {
                const uint32_t off = (uint32_t)((wm + mt * 16 + lrow) * LDA
                                                + s * 16 + lcol8) * 2;
                ldsm_x4(ah[mt], sb + stoff + off);
                ldsm_x4(al[mt], sb + stoff + OFF_ALO + off);
            }
            uint32_t bh[2][4], bl[2][4];
            #pragma unroll
            for (int p = 0; p < 2; ++p) {
                const uint32_t off = (uint32_t)((s * 16 + lrow) * LDB
                                                + wn + p * 16 + lcol8) * 2;
                ldsm_x4_t(bh[p], sb + stoff + OFF_BHI + off);
                ldsm_x4_t(bl[p], sb + stoff + OFF_BLO + off);
            }
            #pragma unroll
            for (int mt = 0; mt < 2; ++mt)
                #pragma unroll
                for (int nt = 0; nt < 4; ++nt) {
                    const uint32_t* Bh = &bh[nt >> 1][(nt & 1) * 2];
                    const uint32_t* Bl = &bl[nt >> 1][(nt & 1) * 2];
                    mma_bf16(acc[mt][nt], ah[mt], Bh);
                    mma_bf16(acc[mt][nt], ah[mt], Bl);
                    mma_bf16(acc[mt][nt], al[mt], Bh);
                }
        }
        __syncthreads();
    }

    #pragma unroll
    for (int mt = 0; mt < 2; ++mt)
        #pragma unroll
        for (int nt = 0; nt < 4; ++nt)
            #pragma unroll
            for (int h = 0; h < 2; ++h) {
                const int row = row0 + wm + mt * 16 + h * 8 + (lane >> 2);
                if (row >= n_out) continue;
                const int col = wn + nt * 8 + (lane & 3) * 2;
                float2 v;
                v.x = acc[mt][nt][h * 2]     + __ldg(&bias[col]);
                v.y = acc[mt][nt][h * 2 + 1] + __ldg(&bias[col + 1]);
                *(float2*)(o_f32 + (size_t)row * 64 + col) = v;
            }
}

// ---------------------------------------------------------------------------
// Merged split: x | W1 | W2 | W3 -> bf16 hi/lo.  Also zeroes tap counters.
// ---------------------------------------------------------------------------
__global__ __launch_bounds__(256) void splitall_kernel(
    const float* __restrict__ x, __nv_bfloat16* __restrict__ xh, __nv_bfloat16* __restrict__ xl, int nx,
    const float* __restrict__ W1, __nv_bfloat16* __restrict__ h1, __nv_bfloat16* __restrict__ l1, int n1,
    const float* __restrict__ W2, __nv_bfloat16* __restrict__ h2, __nv_bfloat16* __restrict__ l2, int n2,
    const float* __restrict__ W3, __nv_bfloat16* __restrict__ h3, __nv_bfloat16* __restrict__ l3, int n3)
{
    if (blockIdx.x == 0) {
        if (threadIdx.x < KT1) g_tapcnt1[threadIdx.x] = 0;
        else if (threadIdx.x < KT1 + KT2) g_tapcnt2[threadIdx.x - KT1] = 0;
    }
    const int total = nx + n1 + n2 + n3;
    for (int i = blockIdx.x * 256 + threadIdx.x; i < total; i += gridDim.x * 256) {
        const float* s; __nv_bfloat16 *hp, *lp; int j;
        if (i < nx)                { s = x;  hp = xh; lp = xl; j = i; }
        else if (i < nx + n1)      { s = W1; hp = h1; lp = l1; j = i - nx; }
        else if (i < nx + n1 + n2) { s = W2; hp = h2; lp = l2; j = i - nx - n1; }
        else                       { s = W3; hp = h3; lp = l3; j = i - nx - n1 - n2; }
        const float v = s[j];
        const __nv_bfloat16 h = __float2bfloat16_rn(v);
        hp[j] = h;
        lp[j] = __float2bfloat16_rn(v - __bfloat162float(h));
    }
}

// ---------------------------------------------------------------------------
extern "C" void kernel_launch(void* const* d_in, const int* in_sizes, int n_in_arrs,
                              void* d_out, int out_size)
{
    const float* x     = (const float*)d_in[0];
    const float* W1    = (const float*)d_in[1];
    const float* b1    = (const float*)d_in[2];
    const float* W2    = (const float*)d_in[3];
    const float* b2    = (const float*)d_in[4];
    const float* W3    = (const float*)d_in[5];
    const float* b3    = (const float*)d_in[6];
    const float* gamma = (const float*)d_in[7];
    const float* beta  = (const float*)d_in[8];
    const float* scale = (const float*)d_in[9];
    const int* nmap1   = (const int*)d_in[10];
    const int* nmap2   = (const int*)d_in[11];
    const int* nmap3   = (const int*)d_in[12];

    const int N    = in_sizes[0] / 96;
    const int N2   = in_sizes[11] / 8;
    const int NB   = (N + 255) / 256;
    const int NB2  = (N2 + 255) / 256;
    const int NRB2 = (N2 + 7) / 8;           // reduce2 blocks = BN partial groups

    __nv_bfloat16 *xh, *xl, *f1h, *f1l, *f2h, *f2l, *w1h, *w1l, *w2h, *w2l, *w3h, *w3l;
    float *st, *bnpart, *bntot;
    int *mask1, *mask2, *tapcnt1, *tapcnt2, *pi1, *pd1, *pi2, *pd2;
    cudaGetSymbolAddress((void**)&xh, g_x_hi);   cudaGetSymbolAddress((void**)&xl, g_x_lo);
    cudaGetSymbolAddress((void**)&f1h, g_f1_hi); cudaGetSymbolAddress((void**)&f1l, g_f1_lo);
    cudaGetSymbolAddress((void**)&f2h, g_f2_hi); cudaGetSymbolAddress((void**)&f2l, g_f2_lo);
    cudaGetSymbolAddress((void**)&w1h, g_w1_hi); cudaGetSymbolAddress((void**)&w1l, g_w1_lo);
    cudaGetSymbolAddress((void**)&w2h, g_w2_hi); cudaGetSymbolAddress((void**)&w2l, g_w2_lo);
    cudaGetSymbolAddress((void**)&w3h, g_w3_hi); cudaGetSymbolAddress((void**)&w3l, g_w3_lo);
    cudaGetSymbolAddress((void**)&st, g_st);
    cudaGetSymbolAddress((void**)&bnpart, g_bnpart);
    cudaGetSymbolAddress((void**)&bntot, g_bntot);
    cudaGetSymbolAddress((void**)&mask1, g_mask1);
    cudaGetSymbolAddress((void**)&mask2, g_mask2);
    cudaGetSymbolAddress((void**)&tapcnt1, g_tapcnt1);
    cudaGetSymbolAddress((void**)&tapcnt2, g_tapcnt2);
    cudaGetSymbolAddress((void**)&pi1, g_pairidx1);
    cudaGetSymbolAddress((void**)&pd1, g_pairdst1);
    cudaGetSymbolAddress((void**)&pi2, g_pairidx2);
    cudaGetSymbolAddress((void**)&pd2, g_pairdst2);

    // prep: merged split (also zeroes both tap counter arrays)
    splitall_kernel<<<512, 256>>>(x, xh, xl, N * 96,
                                  W1, w1h, w1l, 27 * 96 * 64,
                                  W2, w2h, w2l, 8 * 64 * 64,
                                  W3, w3h, w3l, 27 * 64 * 64);

    // ---- compaction preps ----
    emit_fused<KT1, 5><<<NB,  256>>>(nmap1, N,  N, mask1, tapcnt1, pi1, pd1);
    emit_fused<KT2, 3><<<NB2, 256>>>(nmap2, N2, N, mask2, tapcnt2, pi2, pd2);

    // ---- conv1: compacted (27 taps, 96ch), swizzled, 3 CTAs/SM ----
    {
        constexpr int smem = (2 * 128 * 96 + 2 * 96 * 64) * 2;    // 73,728 B
        cudaFuncSetAttribute(conv_compact<96>,
                             cudaFuncAttributeMaxDynamicSharedMemorySize, smem);
        dim3 grid((N + 127) / 128, KT1);
        conv_compact<96><<<grid, 256, smem>>>(xh, xl, w1h, w1l, tapcnt1, pi1, pd1);
    }
    reduce1_kernel<<<(N + 7) / 8, 256>>>(b1, N, mask1, f1h, f1l);

    // ---- conv2: compacted (8 taps, 64ch), swizzled; reduce fuses BN stats ----
    {
        constexpr int smem = (2 * 128 * 64 + 2 * 64 * 64) * 2;    // 49,152 B
        cudaFuncSetAttribute(conv_compact<64>,
                             cudaFuncAttributeMaxDynamicSharedMemorySize, smem);
        dim3 grid((N2 + 127) / 128, KT2);
        conv_compact<64><<<grid, 256, smem>>>(f1h, f1l, w2h, w2l, tapcnt2, pi2, pd2);
    }
    reduce2_bn_kernel<<<NRB2, 256>>>(b2, N2, mask2, f2h, f2l, bnpart);

    // ---- batch norm finalize (two-stage parallel) + apply ----
    bn_sum_kernel<<<128, 256>>>(bnpart, NRB2, bntot);
    bn_st_kernel<<<1, 64>>>(bntot, N2, gamma, beta, scale, st);
    bn_apply_kernel<<<(N2 * 64 + 255) / 256, 256>>>(f2h, f2l, N2, st);

    // ---- conv3: dense, 27 taps, fp32 out ----
    {
        constexpr int stage = (2 * 128 * 72 + 2 * 64 * 72) * 2;
        constexpr int smem  = 2 * stage;                          // 110,592 B
        cudaFuncSetAttribute(sconv_dense<64, 27>,
                             cudaFuncAttributeMaxDynamicSharedMemorySize, smem);
        sconv_dense<64, 27><<<(N2 + 127) / 128, 256, smem>>>(
            f2h, f2l, N2, nmap3, N2, w3h, w3l, b3, (float*)d_out);
    }
}